// round 1
// baseline (speedup 1.0000x reference)
#include <cuda_runtime.h>
#include <math.h>

#define NN 20000
#define EE 320000
#define GG 64
#define INF_ 256
#define H1 512
#define H2C 256
#define HEADS 2
#define CC 16
#define NSTEPS 4
#define KT 4
#define H3 1536

// ---------------- scratch layout (floats) ----------------
constexpr size_t SZ_H    = (size_t)NN * H1;          // 10,240,000
constexpr size_t SZ_SAGG = (size_t)KT * NN * H1;     // 40,960,000
constexpr size_t SZ_GI   = (size_t)NN * H3;          // 30,720,000
constexpr size_t SZ_W3   = (size_t)H1 * H3;

constexpr size_t OFF_H     = 0;
constexpr size_t OFF_SAGG  = OFF_H + SZ_H;
constexpr size_t OFF_A     = OFF_SAGG + SZ_SAGG;
constexpr size_t OFF_GI    = OFF_A + SZ_H;
constexpr size_t OFF_GH    = OFF_GI + SZ_GI;
constexpr size_t OFF_WIHT  = OFF_GH + SZ_GI;
constexpr size_t OFF_WHHT  = OFF_WIHT + SZ_W3;
constexpr size_t OFF_FCWT  = OFF_WHHT + SZ_W3;
constexpr size_t OFF_FEAT  = OFF_FCWT + (size_t)H1 * H1;
constexpr size_t OFF_EL    = OFF_FEAT + SZ_H;
constexpr size_t OFF_ER    = OFF_EL + (size_t)NN * HEADS;
constexpr size_t OFF_EEDGE = OFF_ER + (size_t)NN * HEADS;
constexpr size_t OFF_EEXP  = OFF_EEDGE + (size_t)EE * HEADS;
constexpr size_t OFF_EMAX  = OFF_EEXP + (size_t)EE * HEADS;   // uint storage
constexpr size_t OFF_DEN   = OFF_EMAX + (size_t)NN * HEADS;
constexpr size_t OFF_RST   = OFF_DEN + (size_t)NN * HEADS;
constexpr size_t OFF_HG    = OFF_RST + SZ_H;
constexpr size_t OFF_GCNT  = OFF_HG + (size_t)GG * H1;
constexpr size_t OFF_CNT   = OFF_GCNT + GG;                   // int storage, NN*KT
constexpr size_t TOTAL_F   = OFF_CNT + (size_t)NN * KT;

__device__ __align__(16) float g_buf[TOTAL_F];

// ---------------- helpers ----------------
__device__ __forceinline__ float sigm(float x) { return 1.f / (1.f + expf(-x)); }

__device__ __forceinline__ unsigned fenc(float f) {
    unsigned u = __float_as_uint(f);
    return (u >> 31) ? ~u : (u | 0x80000000u);
}
__device__ __forceinline__ float fdec(unsigned u) {
    return (u >> 31) ? __uint_as_float(u & 0x7fffffffu) : __uint_as_float(~u);
}

// ---------------- generic kernels ----------------
__global__ void zero_f4(float4* p, size_t n4) {
    size_t i = (size_t)blockIdx.x * blockDim.x + threadIdx.x;
    size_t st = (size_t)gridDim.x * blockDim.x;
    for (; i < n4; i += st) p[i] = make_float4(0.f, 0.f, 0.f, 0.f);
}

__global__ void transpose_kernel(const float* __restrict__ in, float* __restrict__ out,
                                 int R, int C) {
    int i = blockIdx.x * blockDim.x + threadIdx.x;
    int tot = R * C;
    int st = gridDim.x * blockDim.x;
    for (; i < tot; i += st) {
        int r = i / C, c = i % C;
        out[(size_t)c * R + r] = in[i];
    }
}

__global__ void pad_kernel(const float* __restrict__ x, float* __restrict__ h) {
    int i = blockIdx.x * blockDim.x + threadIdx.x;
    int st = gridDim.x * blockDim.x;
    int tot = NN * H1;
    for (; i < tot; i += st) {
        int c = i & (H1 - 1);
        int n = i >> 9;
        h[i] = (c < INF_) ? x[(size_t)n * INF_ + c] : 0.f;
    }
}

// ---------------- SGEMM: C[M,N] (+)= A[M,K] @ B[K,N], all row-major ----------------
// BM=BN=128, BK=8, 256 threads, 8x8 per thread. K%8==0, N%128==0 required; M ragged OK.
__global__ __launch_bounds__(256)
void sgemm(const float* __restrict__ A, const float* __restrict__ B,
           float* __restrict__ C, int M, int Kd, int Nd, int accum) {
    __shared__ float As[8][128];
    __shared__ float Bs[8][128];
    int tid = threadIdx.x;
    int bx = blockIdx.x, by = blockIdx.y;
    int arow = tid >> 1, acol = (tid & 1) << 2;
    int brow = tid >> 5, bcol = (tid & 31) << 2;
    int gArow = by * 128 + arow;
    const float* Aptr = A + (size_t)gArow * Kd + acol;
    const float* Bptr = B + (size_t)brow * Nd + (size_t)bx * 128 + bcol;

    float acc[8][8];
#pragma unroll
    for (int i = 0; i < 8; i++)
#pragma unroll
        for (int j = 0; j < 8; j++) acc[i][j] = 0.f;

    int ty = tid >> 4, tx = tid & 15;

    for (int k0 = 0; k0 < Kd; k0 += 8) {
        float4 av = make_float4(0.f, 0.f, 0.f, 0.f);
        if (gArow < M) av = *(const float4*)(Aptr + k0);
        As[acol + 0][arow] = av.x;
        As[acol + 1][arow] = av.y;
        As[acol + 2][arow] = av.z;
        As[acol + 3][arow] = av.w;
        *(float4*)&Bs[brow][bcol] = *(const float4*)(Bptr + (size_t)k0 * Nd);
        __syncthreads();
#pragma unroll
        for (int kk = 0; kk < 8; kk++) {
            float4 a0 = *(float4*)&As[kk][ty * 8];
            float4 a1 = *(float4*)&As[kk][ty * 8 + 4];
            float4 b0 = *(float4*)&Bs[kk][tx * 8];
            float4 b1 = *(float4*)&Bs[kk][tx * 8 + 4];
            float ar[8] = {a0.x, a0.y, a0.z, a0.w, a1.x, a1.y, a1.z, a1.w};
            float br[8] = {b0.x, b0.y, b0.z, b0.w, b1.x, b1.y, b1.z, b1.w};
#pragma unroll
            for (int i = 0; i < 8; i++)
#pragma unroll
                for (int j = 0; j < 8; j++) acc[i][j] = fmaf(ar[i], br[j], acc[i][j]);
        }
        __syncthreads();
    }

    int crow0 = by * 128 + ty * 8;
    int ccol0 = bx * 128 + tx * 8;
#pragma unroll
    for (int i = 0; i < 8; i++) {
        int r = crow0 + i;
        if (r < M) {
            float* cp = C + (size_t)r * Nd + ccol0;
            if (accum) {
                float4 c0 = *(float4*)cp;
                float4 c1 = *(float4*)(cp + 4);
                c0.x += acc[i][0]; c0.y += acc[i][1]; c0.z += acc[i][2]; c0.w += acc[i][3];
                c1.x += acc[i][4]; c1.y += acc[i][5]; c1.z += acc[i][6]; c1.w += acc[i][7];
                *(float4*)cp = c0;
                *(float4*)(cp + 4) = c1;
            } else {
                *(float4*)cp = make_float4(acc[i][0], acc[i][1], acc[i][2], acc[i][3]);
                *(float4*)(cp + 4) = make_float4(acc[i][4], acc[i][5], acc[i][6], acc[i][7]);
            }
        }
    }
}

// ---------------- message aggregation: sagg[k][dst] += h[src], cnt[dst][k]++ ----------------
__global__ void aggregate_kernel(const float* __restrict__ h,
                                 const int* __restrict__ src, const int* __restrict__ dst,
                                 const int* __restrict__ et,
                                 float* __restrict__ sagg, int* __restrict__ cnt) {
    int e = blockIdx.x;
    int s = src[e], d = dst[e], k = et[e];
    if (threadIdx.x == 0) atomicAdd(&cnt[d * KT + k], 1);
    const float* hv = h + (size_t)s * H1;
    float* out = sagg + ((size_t)k * NN + d) * H1;
    int c = threadIdx.x * 4;  // 128 threads * 4 = 512 exactly
    float4 v = *(const float4*)(hv + c);
    atomicAdd(&out[c + 0], v.x);
    atomicAdd(&out[c + 1], v.y);
    atomicAdd(&out[c + 2], v.z);
    atomicAdd(&out[c + 3], v.w);
}

// a[n] = sum_k cnt[n][k] * bmsg[k]
__global__ void bias_a_kernel(const float* __restrict__ bmsg, const int* __restrict__ cnt,
                              float* __restrict__ a) {
    int n = blockIdx.x;
    __shared__ float bm[KT * H1];
    for (int i = threadIdx.x; i < KT * H1; i += blockDim.x) bm[i] = bmsg[i];
    __shared__ int cn[KT];
    if (threadIdx.x < KT) cn[threadIdx.x] = cnt[n * KT + threadIdx.x];
    __syncthreads();
    float c0 = (float)cn[0], c1 = (float)cn[1], c2 = (float)cn[2], c3 = (float)cn[3];
    for (int c = threadIdx.x; c < H1; c += blockDim.x)
        a[(size_t)n * H1 + c] =
            c0 * bm[c] + c1 * bm[H1 + c] + c2 * bm[2 * H1 + c] + c3 * bm[3 * H1 + c];
}

// ---------------- GRU pointwise ----------------
__global__ void gru_kernel(const float* __restrict__ gi, const float* __restrict__ gh,
                           const float* __restrict__ b_ih, const float* __restrict__ b_hh,
                           float* __restrict__ h) {
    int i = blockIdx.x * blockDim.x + threadIdx.x;
    int st = gridDim.x * blockDim.x;
    int tot = NN * H1;
    for (; i < tot; i += st) {
        int n = i >> 9, c = i & (H1 - 1);
        const float* gir = gi + (size_t)n * H3;
        const float* ghr = gh + (size_t)n * H3;
        float r = sigm(gir[c] + b_ih[c] + ghr[c] + b_hh[c]);
        float z = sigm(gir[H1 + c] + b_ih[H1 + c] + ghr[H1 + c] + b_hh[H1 + c]);
        float nn = tanhf(gir[2 * H1 + c] + b_ih[2 * H1 + c] +
                         r * (ghr[2 * H1 + c] + b_hh[2 * H1 + c]));
        h[i] = (1.f - z) * nn + z * h[i];
    }
}

// ---------------- L2 normalize + sigmoid (per node) ----------------
__global__ void norm_sig_kernel(float* __restrict__ h) {
    int n = blockIdx.x;
    int t = threadIdx.x;
    float s = 0.f;
    float* row = h + (size_t)n * H1;
    for (int c = t; c < H1; c += 128) {
        float v = row[c];
        s += v * v;
    }
    __shared__ float sm[128];
    sm[t] = s;
    __syncthreads();
    for (int o = 64; o > 0; o >>= 1) {
        if (t < o) sm[t] += sm[t + o];
        __syncthreads();
    }
    float inv = 1.f / fmaxf(sqrtf(sm[0]), 1e-12f);
    for (int c = t; c < H1; c += 128) row[c] = sigm(row[c] * inv);
}

// ---------------- el/er per node per head ----------------
__global__ void elr_kernel(const float* __restrict__ feat, const float* __restrict__ attn_l,
                           const float* __restrict__ attn_r,
                           float* __restrict__ el, float* __restrict__ er) {
    int n = blockIdx.x;
    int t = threadIdx.x;  // 256
    float f0 = feat[(size_t)n * H1 + t];
    float f1 = feat[(size_t)n * H1 + H2C + t];
    float vals[4] = {f0 * attn_l[t], f0 * attn_r[t], f1 * attn_l[H2C + t], f1 * attn_r[H2C + t]};
    float outp[4];
    __shared__ float sm[256];
#pragma unroll
    for (int q = 0; q < 4; q++) {
        sm[t] = vals[q];
        __syncthreads();
        for (int o = 128; o > 0; o >>= 1) {
            if (t < o) sm[t] += sm[t + o];
            __syncthreads();
        }
        outp[q] = sm[0];
        __syncthreads();
    }
    if (t == 0) {
        el[n * 2] = outp[0];
        er[n * 2] = outp[1];
        el[n * 2 + 1] = outp[2];
        er[n * 2 + 1] = outp[3];
    }
}

// ---------------- edge softmax passes ----------------
__global__ void edge_max_kernel(const int* __restrict__ src, const int* __restrict__ dst,
                                const float* __restrict__ el, const float* __restrict__ er,
                                float* __restrict__ eedge, unsigned* __restrict__ emax) {
    int e = blockIdx.x * blockDim.x + threadIdx.x;
    if (e >= EE) return;
    int s = src[e], d = dst[e];
#pragma unroll
    for (int hd = 0; hd < HEADS; hd++) {
        float v = el[s * 2 + hd] + er[d * 2 + hd];
        v = v > 0.f ? v : 0.2f * v;
        eedge[e * 2 + hd] = v;
        atomicMax(&emax[d * 2 + hd], fenc(v));
    }
}

__global__ void edge_exp_kernel(const int* __restrict__ dst, const float* __restrict__ eedge,
                                const unsigned* __restrict__ emax,
                                float* __restrict__ eexp, float* __restrict__ den) {
    int e = blockIdx.x * blockDim.x + threadIdx.x;
    if (e >= EE) return;
    int d = dst[e];
#pragma unroll
    for (int hd = 0; hd < HEADS; hd++) {
        float ee = expf(eedge[e * 2 + hd] - fdec(emax[d * 2 + hd]));
        eexp[e * 2 + hd] = ee;
        atomicAdd(&den[d * 2 + hd], ee);
    }
}

__global__ void edge_scatter_kernel(const int* __restrict__ src, const int* __restrict__ dst,
                                    const float* __restrict__ eexp, const float* __restrict__ den,
                                    const float* __restrict__ feat, float* __restrict__ rst) {
    int e = blockIdx.x;
    int s = src[e], d = dst[e];
    float a0 = eexp[e * 2] / den[d * 2];
    float a1 = eexp[e * 2 + 1] / den[d * 2 + 1];
    const float* f = feat + (size_t)s * H1;
    float* r = rst + (size_t)d * H1;
    int c = threadIdx.x * 4;  // 128 threads * 4 = 512
    float al = (c < H2C) ? a0 : a1;
    float4 v = *(const float4*)(f + c);
    atomicAdd(&r[c + 0], al * v.x);
    atomicAdd(&r[c + 1], al * v.y);
    atomicAdd(&r[c + 2], al * v.z);
    atomicAdd(&r[c + 3], al * v.w);
}

// ---------------- graph mean + classify ----------------
__global__ void gcnt_kernel(const int* __restrict__ gid, float* __restrict__ gcnt) {
    int n = blockIdx.x * blockDim.x + threadIdx.x;
    if (n < NN) atomicAdd(&gcnt[gid[n]], 1.f);
}

__global__ void graph_accum_kernel(const int* __restrict__ gid, const float* __restrict__ rst,
                                   const float* __restrict__ gat_bias, float* __restrict__ hg) {
    int i = blockIdx.x * blockDim.x + threadIdx.x;
    int st = gridDim.x * blockDim.x;
    int tot = NN * H1;
    for (; i < tot; i += st) {
        int n = i >> 9, c = i & (H1 - 1);
        float v = rst[i] + gat_bias[c];
        v = fmaxf(v, 0.f);
        atomicAdd(&hg[(size_t)gid[n] * H1 + c], v);
    }
}

__global__ void final_kernel(const float* __restrict__ hg, const float* __restrict__ gcnt,
                             const float* __restrict__ cw, const float* __restrict__ cb,
                             float* __restrict__ out) {
    int g = blockIdx.x >> 1, hd = blockIdx.x & 1;
    int t = threadIdx.x;  // 256
    __shared__ float row[H2C];
    float inv = 1.f / fmaxf(gcnt[g], 1.f);
    row[t] = hg[(size_t)g * H1 + hd * H2C + t] * inv;
    __syncthreads();
    if (t < CC) {
        float s = cb[t];
        for (int j = 0; j < H2C; j++) s += row[j] * cw[t * H2C + j];
        out[((size_t)g * HEADS + hd) * CC + t] = s;
    }
}

// ---------------- launch ----------------
extern "C" void kernel_launch(void* const* d_in, const int* in_sizes, int n_in,
                              void* d_out, int out_size) {
    const float* in_feat  = (const float*)d_in[0];
    const int*   src      = (const int*)d_in[1];
    const int*   dst      = (const int*)d_in[2];
    const int*   etype    = (const int*)d_in[3];
    const int*   gid      = (const int*)d_in[4];
    const float* Wmsg     = (const float*)d_in[5];
    const float* bmsg     = (const float*)d_in[6];
    const float* w_ih     = (const float*)d_in[7];
    const float* w_hh     = (const float*)d_in[8];
    const float* b_ih     = (const float*)d_in[9];
    const float* b_hh     = (const float*)d_in[10];
    const float* fc_w     = (const float*)d_in[11];
    const float* attn_l   = (const float*)d_in[12];
    const float* attn_r   = (const float*)d_in[13];
    const float* gat_bias = (const float*)d_in[14];
    const float* cw       = (const float*)d_in[15];
    const float* cb       = (const float*)d_in[16];
    float* out = (float*)d_out;

    float* base = nullptr;
    cudaGetSymbolAddress((void**)&base, g_buf);

    float*    h     = base + OFF_H;
    float*    sagg  = base + OFF_SAGG;
    float*    a     = base + OFF_A;
    float*    gi    = base + OFF_GI;
    float*    gh    = base + OFF_GH;
    float*    wihT  = base + OFF_WIHT;
    float*    whhT  = base + OFF_WHHT;
    float*    fcwT  = base + OFF_FCWT;
    float*    feat  = base + OFF_FEAT;
    float*    el    = base + OFF_EL;
    float*    er    = base + OFF_ER;
    float*    eedge = base + OFF_EEDGE;
    float*    eexp  = base + OFF_EEXP;
    unsigned* emax  = (unsigned*)(base + OFF_EMAX);
    float*    den   = base + OFF_DEN;
    float*    rst   = base + OFF_RST;
    float*    hg    = base + OFF_HG;
    float*    gcnt  = base + OFF_GCNT;
    int*      cnt   = (int*)(base + OFF_CNT);

    // weight transposes (NN-form GEMMs everywhere)
    transpose_kernel<<<512, 256>>>(w_ih, wihT, H3, H1);
    transpose_kernel<<<512, 256>>>(w_hh, whhT, H3, H1);
    transpose_kernel<<<256, 256>>>(fc_w, fcwT, H1, H1);
    pad_kernel<<<4096, 256>>>(in_feat, h);

    dim3 g4(H1 / 128, (NN + 127) / 128);   // N=512
    dim3 g12(H3 / 128, (NN + 127) / 128);  // N=1536

    for (int step = 0; step < NSTEPS; step++) {
        zero_f4<<<4096, 256>>>((float4*)sagg, SZ_SAGG / 4);
        zero_f4<<<64, 256>>>((float4*)cnt, ((size_t)NN * KT) / 4);
        aggregate_kernel<<<EE, 128>>>(h, src, dst, etype, sagg, cnt);
        bias_a_kernel<<<NN, 256>>>(bmsg, cnt, a);
        for (int k = 0; k < KT; k++)
            sgemm<<<g4, 256>>>(sagg + (size_t)k * NN * H1, Wmsg + (size_t)k * H1 * H1,
                               a, NN, H1, H1, 1);
        sgemm<<<g12, 256>>>(a, wihT, gi, NN, H1, H3, 0);
        sgemm<<<g12, 256>>>(h, whhT, gh, NN, H1, H3, 0);
        gru_kernel<<<4096, 256>>>(gi, gh, b_ih, b_hh, h);
    }

    norm_sig_kernel<<<NN, 128>>>(h);
    sgemm<<<g4, 256>>>(h, fcwT, feat, NN, H1, H1, 0);
    elr_kernel<<<NN, 256>>>(feat, attn_l, attn_r, el, er);

    // emax + den are contiguous: zero both (emax encoded 0 == -inf sentinel)
    zero_f4<<<64, 256>>>((float4*)emax, (2 * (size_t)NN * HEADS) / 4);
    edge_max_kernel<<<(EE + 255) / 256, 256>>>(src, dst, el, er, eedge, emax);
    edge_exp_kernel<<<(EE + 255) / 256, 256>>>(dst, eedge, emax, eexp, den);

    zero_f4<<<2048, 256>>>((float4*)rst, SZ_H / 4);
    edge_scatter_kernel<<<EE, 128>>>(src, dst, eexp, den, feat, rst);

    // hg + gcnt contiguous
    zero_f4<<<32, 256>>>((float4*)hg, ((size_t)GG * H1 + GG) / 4);
    gcnt_kernel<<<(NN + 255) / 256, 256>>>(gid, gcnt);
    graph_accum_kernel<<<4096, 256>>>(gid, rst, gat_bias, hg);
    final_kernel<<<GG * HEADS, 256>>>(hg, gcnt, cw, cb, out);
}